// round 1
// baseline (speedup 1.0000x reference)
#include <cuda_runtime.h>
#include <math.h>

#define BATCH  4
#define SEQ    1024
#define DMODEL 1024
#define NH     16
#define HD     64

// ---------------- scratch (no cudaMalloc allowed) ----------------
__device__ float g_q[BATCH*NH*SEQ*HD];     // [B,H,S,DK]
__device__ float g_k[BATCH*NH*SEQ*HD];
__device__ float g_v[BATCH*NH*SEQ*HD];
__device__ float g_ctx[BATCH*SEQ*DMODEL];  // [B,S,H*DK]
__device__ float g_bias[NH*2048];          // bias per (h, rel+1023)

// ---------------- relative-position bias table ----------------
__global__ void bias_kernel(const float* __restrict__ rel_emb)
{
    int t = blockIdx.x * blockDim.x + threadIdx.x;
    if (t >= NH * 2047) return;
    int h   = t / 2047;
    int rel = (t % 2047) - 1023;      // rel = key_pos - query_pos
    int n   = -rel;                    // matches reference: n = -relative_position
    int ret = 0;
    if (n < 0) { ret = 16; n = -n; }
    int bkt;
    if (n < 8) {
        bkt = n;
    } else {
        float v = logf((float)n * 0.125f) / logf(16.0f) * 8.0f;
        int vi = (int)v;               // truncation, matches astype(int32) for v>=0
        bkt = 8 + (vi < 7 ? vi : 7);   // == min(8+vi, 15)
    }
    g_bias[h*2048 + rel + 1023] = rel_emb[(ret + bkt)*NH + h];
}

// ---------------- 128x128x8 fp32 SGEMM ----------------
// A: [4096 x 1024] row-major, B: [1024 x 1024] row-major.
// headMap=1: C index = ((b*16+h)*1024 + s)*64 + d  with m=b*1024+s, n=h*64+d
// headMap=0: plain row-major [4096 x 1024]
__global__ __launch_bounds__(256, 2)
void sgemm128(const float* __restrict__ A, const float* __restrict__ B,
              float* __restrict__ C, int headMap)
{
    __shared__ float As[8][128];
    __shared__ float Bs[8][128];

    const int tid = threadIdx.x;
    const int tx = tid & 15, ty = tid >> 4;
    const int m0 = blockIdx.y * 128;
    const int n0 = blockIdx.x * 128;

    const int a_row = tid >> 1;          // 0..127
    const int a_col = (tid & 1) * 4;     // 0 or 4
    const int b_row = tid >> 5;          // 0..7
    const int b_col = (tid & 31) * 4;    // 0..124

    const float* Ap = A + (size_t)(m0 + a_row) * DMODEL + a_col;
    const float* Bp = B + (size_t)b_row * DMODEL + n0 + b_col;

    float acc[8][8];
    #pragma unroll
    for (int i = 0; i < 8; i++)
        #pragma unroll
        for (int j = 0; j < 8; j++) acc[i][j] = 0.f;

    for (int k0 = 0; k0 < DMODEL; k0 += 8) {
        float4 av = *(const float4*)(Ap + k0);
        float4 bv = *(const float4*)(Bp + (size_t)k0 * DMODEL);
        __syncthreads();
        As[a_col+0][a_row] = av.x;
        As[a_col+1][a_row] = av.y;
        As[a_col+2][a_row] = av.z;
        As[a_col+3][a_row] = av.w;
        *(float4*)&Bs[b_row][b_col] = bv;
        __syncthreads();

        #pragma unroll
        for (int kk = 0; kk < 8; kk++) {
            float a[8], b[8];
            #pragma unroll
            for (int i = 0; i < 4; i++) {
                a[i]   = As[kk][ty*4 + i];
                a[i+4] = As[kk][64 + ty*4 + i];
            }
            #pragma unroll
            for (int j = 0; j < 4; j++) {
                b[j]   = Bs[kk][tx*4 + j];
                b[j+4] = Bs[kk][64 + tx*4 + j];
            }
            #pragma unroll
            for (int i = 0; i < 8; i++)
                #pragma unroll
                for (int j = 0; j < 8; j++)
                    acc[i][j] += a[i] * b[j];
        }
    }

    #pragma unroll
    for (int i = 0; i < 8; i++) {
        int m = m0 + ((i < 4) ? (ty*4 + i) : (64 + ty*4 + (i - 4)));
        #pragma unroll
        for (int j = 0; j < 8; j++) {
            int n = n0 + ((j < 4) ? (tx*4 + j) : (64 + tx*4 + (j - 4)));
            size_t idx;
            if (headMap)
                idx = (size_t)((m >> 10) * NH + (n >> 6)) * (SEQ * HD)
                    + (size_t)(m & 1023) * HD + (n & 63);
            else
                idx = (size_t)m * DMODEL + n;
            C[idx] = acc[i][j];
        }
    }
}

// ---------------- flash-style attention + bias ----------------
#define TCOLS 65
__global__ __launch_bounds__(256, 2)
void attn_kernel()
{
    extern __shared__ float sm[];
    float* Qs     = sm;                    // 64*65
    float* KVs    = Qs  + 64 * TCOLS;      // 64*65 (K, then reused for V)
    float* Ps     = KVs + 64 * TCOLS;      // 64*65
    float* m_s    = Ps  + 64 * TCOLS;      // 64
    float* l_s    = m_s + 64;              // 64
    float* sc_s   = l_s + 64;              // 64
    float* bias_s = sc_s + 64;             // 128 (127 used)

    const int tid = threadIdx.x;
    const int tx = tid & 15, ty = tid >> 4;
    const int q0 = blockIdx.x * 64;
    const int h  = blockIdx.y;
    const int b  = blockIdx.z;

    const float* Qg = g_q + (size_t)(b*NH + h) * SEQ * HD;
    const float* Kg = g_k + (size_t)(b*NH + h) * SEQ * HD;
    const float* Vg = g_v + (size_t)(b*NH + h) * SEQ * HD;

    // load Q tile (64 x 64)
    for (int i = tid; i < 64 * HD / 4; i += 256) {
        int r = i >> 4, c = (i & 15) * 4;
        float4 v = *(const float4*)(Qg + (size_t)(q0 + r) * HD + c);
        Qs[r*TCOLS + c + 0] = v.x;
        Qs[r*TCOLS + c + 1] = v.y;
        Qs[r*TCOLS + c + 2] = v.z;
        Qs[r*TCOLS + c + 3] = v.w;
    }
    if (tid < 64) { m_s[tid] = -1e30f; l_s[tid] = 0.f; }

    float acc[4][4];
    #pragma unroll
    for (int i = 0; i < 4; i++)
        #pragma unroll
        for (int j = 0; j < 4; j++) acc[i][j] = 0.f;

    for (int kc = 0; kc < SEQ / 64; kc++) {
        const int k0 = kc * 64;
        __syncthreads();  // previous chunk fully consumed

        // load K chunk
        for (int i = tid; i < 64 * HD / 4; i += 256) {
            int r = i >> 4, c = (i & 15) * 4;
            float4 v = *(const float4*)(Kg + (size_t)(k0 + r) * HD + c);
            KVs[r*TCOLS + c + 0] = v.x;
            KVs[r*TCOLS + c + 1] = v.y;
            KVs[r*TCOLS + c + 2] = v.z;
            KVs[r*TCOLS + c + 3] = v.w;
        }
        // bias window: rel = (k0+cc) - (q0+rr), cc,rr in [0,63] -> 127 values
        if (tid < 127)
            bias_s[tid] = g_bias[h*2048 + (k0 - q0 + tid - 63) + 1023];
        __syncthreads();

        // scores 4x4 per thread: rows ty*4+i, cols tx*4+j
        float s[4][4];
        #pragma unroll
        for (int i = 0; i < 4; i++)
            #pragma unroll
            for (int j = 0; j < 4; j++) s[i][j] = 0.f;

        for (int d = 0; d < HD; d++) {
            float qf[4], kf[4];
            #pragma unroll
            for (int i = 0; i < 4; i++) qf[i] = Qs[(ty*4 + i)*TCOLS + d];
            #pragma unroll
            for (int j = 0; j < 4; j++) kf[j] = KVs[(tx*4 + j)*TCOLS + d];
            #pragma unroll
            for (int i = 0; i < 4; i++)
                #pragma unroll
                for (int j = 0; j < 4; j++)
                    s[i][j] += qf[i] * kf[j];
        }
        #pragma unroll
        for (int i = 0; i < 4; i++)
            #pragma unroll
            for (int j = 0; j < 4; j++)
                s[i][j] += bias_s[63 + (tx*4 + j) - (ty*4 + i)];

        // online softmax; row r handled by 16 contiguous lanes of one warp
        #pragma unroll
        for (int i = 0; i < 4; i++) {
            int r = ty*4 + i;
            float rmax = fmaxf(fmaxf(s[i][0], s[i][1]), fmaxf(s[i][2], s[i][3]));
            #pragma unroll
            for (int o = 8; o; o >>= 1)
                rmax = fmaxf(rmax, __shfl_xor_sync(0xffffffffu, rmax, o));
            float mold = m_s[r];
            float mnew = fmaxf(mold, rmax);
            float rsum = 0.f;
            #pragma unroll
            for (int j = 0; j < 4; j++) {
                s[i][j] = __expf(s[i][j] - mnew);
                rsum += s[i][j];
            }
            #pragma unroll
            for (int o = 8; o; o >>= 1)
                rsum += __shfl_xor_sync(0xffffffffu, rsum, o);
            if (tx == 0) {
                float scale = __expf(mold - mnew);
                sc_s[r] = scale;
                l_s[r]  = l_s[r] * scale + rsum;
                m_s[r]  = mnew;
            }
        }
        __syncthreads();  // done reading K from KVs; stats settled

        // write P, load V chunk (overwrites K)
        #pragma unroll
        for (int i = 0; i < 4; i++)
            #pragma unroll
            for (int j = 0; j < 4; j++)
                Ps[(ty*4 + i)*TCOLS + tx*4 + j] = s[i][j];
        for (int i = tid; i < 64 * HD / 4; i += 256) {
            int r = i >> 4, c = (i & 15) * 4;
            float4 v = *(const float4*)(Vg + (size_t)(k0 + r) * HD + c);
            KVs[r*TCOLS + c + 0] = v.x;
            KVs[r*TCOLS + c + 1] = v.y;
            KVs[r*TCOLS + c + 2] = v.z;
            KVs[r*TCOLS + c + 3] = v.w;
        }
        __syncthreads();

        // rescale accumulator + P @ V  (rows ty*4+i, d-cols tx*4+j)
        float scr[4];
        #pragma unroll
        for (int i = 0; i < 4; i++) scr[i] = sc_s[ty*4 + i];
        #pragma unroll
        for (int i = 0; i < 4; i++)
            #pragma unroll
            for (int j = 0; j < 4; j++) acc[i][j] *= scr[i];

        for (int jj = 0; jj < 64; jj++) {
            float pf[4], vf[4];
            #pragma unroll
            for (int i = 0; i < 4; i++) pf[i] = Ps[(ty*4 + i)*TCOLS + jj];
            #pragma unroll
            for (int j = 0; j < 4; j++) vf[j] = KVs[jj*TCOLS + tx*4 + j];
            #pragma unroll
            for (int i = 0; i < 4; i++)
                #pragma unroll
                for (int j = 0; j < 4; j++)
                    acc[i][j] += pf[i] * vf[j];
        }
    }

    __syncthreads();
    #pragma unroll
    for (int i = 0; i < 4; i++) {
        int r = ty*4 + i;
        float inv = 1.0f / l_s[r];
        #pragma unroll
        for (int j = 0; j < 4; j++) {
            g_ctx[((size_t)b * SEQ + q0 + r) * DMODEL + h*HD + tx*4 + j] = acc[i][j] * inv;
        }
    }
}

// ---------------- launch ----------------
extern "C" void kernel_launch(void* const* d_in, const int* in_sizes, int n_in,
                              void* d_out, int out_size)
{
    const float* x    = (const float*)d_in[0];
    const float* Wq   = (const float*)d_in[1];
    const float* Wk   = (const float*)d_in[2];
    const float* Wv   = (const float*)d_in[3];
    const float* Wo   = (const float*)d_in[4];
    const float* relE = (const float*)d_in[5];
    float* out = (float*)d_out;

    float *pq, *pk, *pv, *pctx;
    cudaGetSymbolAddress((void**)&pq,   g_q);
    cudaGetSymbolAddress((void**)&pk,   g_k);
    cudaGetSymbolAddress((void**)&pv,   g_v);
    cudaGetSymbolAddress((void**)&pctx, g_ctx);

    bias_kernel<<<(NH*2047 + 255)/256, 256>>>(relE);

    dim3 gg(DMODEL/128, (BATCH*SEQ)/128);   // (8, 32)
    sgemm128<<<gg, 256>>>(x, Wq, pq, 1);
    sgemm128<<<gg, 256>>>(x, Wk, pk, 1);
    sgemm128<<<gg, 256>>>(x, Wv, pv, 1);

    cudaFuncSetAttribute(attn_kernel, cudaFuncAttributeMaxDynamicSharedMemorySize, 51200);
    attn_kernel<<<dim3(SEQ/64, NH, BATCH), 256, 51200>>>();

    sgemm128<<<gg, 256>>>(pctx, Wo, out, 0);
}

// round 3
// speedup vs baseline: 1.4756x; 1.4756x over previous
#include <cuda_runtime.h>
#include <cuda_bf16.h>
#include <cstdint>
#include <math.h>

#define BATCH  4
#define SEQ    1024
#define DMODEL 1024
#define NH     16
#define HD     64
#define MTOT   (BATCH*SEQ)

// ---------------- scratch ----------------
__device__ float g_q[BATCH*NH*SEQ*HD];
__device__ float g_k[BATCH*NH*SEQ*HD];
__device__ float g_v[BATCH*NH*SEQ*HD];
__device__ float g_ctx[MTOT*DMODEL];
__device__ float g_bias[NH*2048];
__device__ __nv_bfloat16 g_xh[MTOT*DMODEL], g_xl[MTOT*DMODEL];
__device__ __nv_bfloat16 g_wh[4*DMODEL*DMODEL], g_wl[4*DMODEL*DMODEL];
__device__ __nv_bfloat16 g_ch[MTOT*DMODEL], g_cl[MTOT*DMODEL];

// ---------------- bias table ----------------
__global__ void bias_kernel(const float* __restrict__ rel_emb)
{
    int t = blockIdx.x * blockDim.x + threadIdx.x;
    if (t >= NH * 2047) return;
    int h   = t / 2047;
    int rel = (t % 2047) - 1023;
    int n   = -rel;
    int ret = 0;
    if (n < 0) { ret = 16; n = -n; }
    int bkt;
    if (n < 8) {
        bkt = n;
    } else {
        float v = logf((float)n * 0.125f) / logf(16.0f) * 8.0f;
        int vi = (int)v;
        bkt = 8 + (vi < 7 ? vi : 7);
    }
    g_bias[h*2048 + rel + 1023] = rel_emb[(ret + bkt)*NH + h];
}

// ---------------- fp32 -> bf16 hi/lo split ----------------
__global__ void split_kernel(const float* __restrict__ src,
                             __nv_bfloat16* __restrict__ hi,
                             __nv_bfloat16* __restrict__ lo, int n4)
{
    int i = blockIdx.x * blockDim.x + threadIdx.x;
    if (i >= n4) return;
    float4 v = ((const float4*)src)[i];
    __nv_bfloat16 h[4], l[4];
    float vv[4] = {v.x, v.y, v.z, v.w};
    #pragma unroll
    for (int j = 0; j < 4; j++) {
        h[j] = __float2bfloat16(vv[j]);
        l[j] = __float2bfloat16(vv[j] - __bfloat162float(h[j]));
    }
    ((uint2*)hi)[i] = *(uint2*)h;
    ((uint2*)lo)[i] = *(uint2*)l;
}

// ---------------- tensor-core split-bf16 GEMM ----------------
// C[M=4096, N=1024] = A[4096,1024] @ B[1024,1024], fp32 out
// 3-term: Ah*Bh + Ah*Bl + Al*Bh
#define LDSM4(r, addr) asm volatile( \
    "ldmatrix.sync.aligned.m8n8.x4.shared.b16 {%0,%1,%2,%3}, [%4];" \
    : "=r"(r[0]),"=r"(r[1]),"=r"(r[2]),"=r"(r[3]) : "r"(addr))
#define LDSM2T(r, addr) asm volatile( \
    "ldmatrix.sync.aligned.m8n8.x2.trans.shared.b16 {%0,%1}, [%2];" \
    : "=r"(r[0]),"=r"(r[1]) : "r"(addr))
#define MMA16816(d, a, b) asm volatile( \
    "mma.sync.aligned.m16n8k16.row.col.f32.bf16.bf16.f32 " \
    "{%0,%1,%2,%3},{%4,%5,%6,%7},{%8,%9},{%0,%1,%2,%3};" \
    : "+f"(d[0]),"+f"(d[1]),"+f"(d[2]),"+f"(d[3]) \
    : "r"(a[0]),"r"(a[1]),"r"(a[2]),"r"(a[3]),"r"(b[0]),"r"(b[1]))
#define CPASYNC16(dst, src) asm volatile( \
    "cp.async.cg.shared.global [%0], [%1], 16;" :: "r"(dst), "l"(src) : "memory")

// smem layout (bytes), per stage 37888:
//   A_hi: 128 rows * 80B  = 10240 @ 0
//   A_lo: 10240           @ 10240
//   B_hi: 32 rows * 272B  = 8704  @ 20480
//   B_lo: 8704            @ 29184
#define STAGE_BYTES 37888
__device__ __forceinline__ unsigned aOff(int buf, int arr, int row, int col) {
    return (unsigned)(buf*STAGE_BYTES + arr*10240 + row*80 + col*2);
}
__device__ __forceinline__ unsigned bOff(int buf, int arr, int row, int col) {
    return (unsigned)(buf*STAGE_BYTES + 20480 + arr*8704 + row*272 + col*2);
}

__global__ __launch_bounds__(256)
void gemm_bf16split(const __nv_bfloat16* __restrict__ Ah,
                    const __nv_bfloat16* __restrict__ Al,
                    const __nv_bfloat16* __restrict__ Bh,
                    const __nv_bfloat16* __restrict__ Bl,
                    float* __restrict__ C, int headMap)
{
    extern __shared__ __align__(16) char smem_raw[];
    unsigned sbase = (unsigned)__cvta_generic_to_shared(smem_raw);

    const int tid  = threadIdx.x;
    const int wid  = tid >> 5, lane = tid & 31;
    const int wm0  = (wid & 3) * 32;
    const int wn0  = (wid >> 2) * 64;
    const int m0   = blockIdx.y * 128;
    const int n0   = blockIdx.x * 128;

    float acc[2][8][4];
    #pragma unroll
    for (int mi = 0; mi < 2; mi++)
        #pragma unroll
        for (int ni = 0; ni < 8; ni++)
            #pragma unroll
            for (int r = 0; r < 4; r++) acc[mi][ni][r] = 0.f;

    // issue first stage
    {
        const int k0 = 0;
        #pragma unroll
        for (int u = 0; u < 2; u++) {
            int t = tid + u*256;
            int r = t >> 2, c = (t & 3) * 8;
            CPASYNC16(sbase + aOff(0,0,r,c), Ah + (size_t)(m0+r)*DMODEL + k0 + c);
            CPASYNC16(sbase + aOff(0,1,r,c), Al + (size_t)(m0+r)*DMODEL + k0 + c);
            int r2 = t >> 4, c2 = (t & 15) * 8;
            CPASYNC16(sbase + bOff(0,0,r2,c2), Bh + (size_t)(k0+r2)*DMODEL + n0 + c2);
            CPASYNC16(sbase + bOff(0,1,r2,c2), Bl + (size_t)(k0+r2)*DMODEL + n0 + c2);
        }
        asm volatile("cp.async.commit_group;" ::: "memory");
    }

    int buf = 0;
    for (int it = 0; it < DMODEL/32; it++) {
        if (it < DMODEL/32 - 1) {
            const int k0 = (it + 1) * 32;
            const int nb = buf ^ 1;
            #pragma unroll
            for (int u = 0; u < 2; u++) {
                int t = tid + u*256;
                int r = t >> 2, c = (t & 3) * 8;
                CPASYNC16(sbase + aOff(nb,0,r,c), Ah + (size_t)(m0+r)*DMODEL + k0 + c);
                CPASYNC16(sbase + aOff(nb,1,r,c), Al + (size_t)(m0+r)*DMODEL + k0 + c);
                int r2 = t >> 4, c2 = (t & 15) * 8;
                CPASYNC16(sbase + bOff(nb,0,r2,c2), Bh + (size_t)(k0+r2)*DMODEL + n0 + c2);
                CPASYNC16(sbase + bOff(nb,1,r2,c2), Bl + (size_t)(k0+r2)*DMODEL + n0 + c2);
            }
            asm volatile("cp.async.commit_group;" ::: "memory");
            asm volatile("cp.async.wait_group 1;" ::: "memory");
        } else {
            asm volatile("cp.async.wait_group 0;" ::: "memory");
        }
        __syncthreads();

        #pragma unroll
        for (int ks = 0; ks < 2; ks++) {
            unsigned afh[2][4], afl[2][4];
            #pragma unroll
            for (int mi = 0; mi < 2; mi++) {
                int row = wm0 + mi*16 + (lane & 15);
                int col = ks*16 + (lane >> 4) * 8;
                LDSM4(afh[mi], sbase + aOff(buf,0,row,col));
                LDSM4(afl[mi], sbase + aOff(buf,1,row,col));
            }
            unsigned bfh[8][2], bfl[8][2];
            #pragma unroll
            for (int ni = 0; ni < 8; ni++) {
                int row = ks*16 + (lane & 15);
                int col = wn0 + ni*8;
                LDSM2T(bfh[ni], sbase + bOff(buf,0,row,col));
                LDSM2T(bfl[ni], sbase + bOff(buf,1,row,col));
            }
            #pragma unroll
            for (int mi = 0; mi < 2; mi++)
                #pragma unroll
                for (int ni = 0; ni < 8; ni++) {
                    MMA16816(acc[mi][ni], afh[mi], bfh[ni]);
                    MMA16816(acc[mi][ni], afh[mi], bfl[ni]);
                    MMA16816(acc[mi][ni], afl[mi], bfh[ni]);
                }
        }
        __syncthreads();
        buf ^= 1;
    }

    // epilogue
    const int r  = lane >> 2;
    const int c2 = (lane & 3) * 2;
    #pragma unroll
    for (int mi = 0; mi < 2; mi++) {
        #pragma unroll
        for (int ni = 0; ni < 8; ni++) {
            int n = n0 + wn0 + ni*8 + c2;
            #pragma unroll
            for (int half = 0; half < 2; half++) {
                int m = m0 + wm0 + mi*16 + r + half*8;
                float2 v = make_float2(acc[mi][ni][half*2], acc[mi][ni][half*2+1]);
                size_t idx;
                if (headMap)
                    idx = (size_t)((m >> 10) * NH + (n >> 6)) * (SEQ * HD)
                        + (size_t)(m & 1023) * HD + (n & 63);
                else
                    idx = (size_t)m * DMODEL + n;
                *(float2*)(C + idx) = v;
            }
        }
    }
}

// ---------------- flash-style attention + bias (fp32) ----------------
#define TCOLS 65
__global__ __launch_bounds__(256, 2)
void attn_kernel()
{
    extern __shared__ float sm[];
    float* Qs     = sm;
    float* KVs    = Qs  + 64 * TCOLS;
    float* Ps     = KVs + 64 * TCOLS;
    float* m_s    = Ps  + 64 * TCOLS;
    float* l_s    = m_s + 64;
    float* sc_s   = l_s + 64;
    float* bias_s = sc_s + 64;

    const int tid = threadIdx.x;
    const int tx = tid & 15, ty = tid >> 4;
    const int q0 = blockIdx.x * 64;
    const int h  = blockIdx.y;
    const int b  = blockIdx.z;

    const float* Qg = g_q + (size_t)(b*NH + h) * SEQ * HD;
    const float* Kg = g_k + (size_t)(b*NH + h) * SEQ * HD;
    const float* Vg = g_v + (size_t)(b*NH + h) * SEQ * HD;

    for (int i = tid; i < 64 * HD / 4; i += 256) {
        int r = i >> 4, c = (i & 15) * 4;
        float4 v = *(const float4*)(Qg + (size_t)(q0 + r) * HD + c);
        Qs[r*TCOLS + c + 0] = v.x;
        Qs[r*TCOLS + c + 1] = v.y;
        Qs[r*TCOLS + c + 2] = v.z;
        Qs[r*TCOLS + c + 3] = v.w;
    }
    if (tid < 64) { m_s[tid] = -1e30f; l_s[tid] = 0.f; }

    float acc[4][4];
    #pragma unroll
    for (int i = 0; i < 4; i++)
        #pragma unroll
        for (int j = 0; j < 4; j++) acc[i][j] = 0.f;

    for (int kc = 0; kc < SEQ / 64; kc++) {
        const int k0 = kc * 64;
        __syncthreads();

        for (int i = tid; i < 64 * HD / 4; i += 256) {
            int r = i >> 4, c = (i & 15) * 4;
            float4 v = *(const float4*)(Kg + (size_t)(k0 + r) * HD + c);
            KVs[r*TCOLS + c + 0] = v.x;
            KVs[r*TCOLS + c + 1] = v.y;
            KVs[r*TCOLS + c + 2] = v.z;
            KVs[r*TCOLS + c + 3] = v.w;
        }
        if (tid < 127)
            bias_s[tid] = g_bias[h*2048 + (k0 - q0 + tid - 63) + 1023];
        __syncthreads();

        float s[4][4];
        #pragma unroll
        for (int i = 0; i < 4; i++)
            #pragma unroll
            for (int j = 0; j < 4; j++) s[i][j] = 0.f;

        for (int d = 0; d < HD; d++) {
            float qf[4], kf[4];
            #pragma unroll
            for (int i = 0; i < 4; i++) qf[i] = Qs[(ty*4 + i)*TCOLS + d];
            #pragma unroll
            for (int j = 0; j < 4; j++) kf[j] = KVs[(tx*4 + j)*TCOLS + d];
            #pragma unroll
            for (int i = 0; i < 4; i++)
                #pragma unroll
                for (int j = 0; j < 4; j++)
                    s[i][j] += qf[i] * kf[j];
        }
        #pragma unroll
        for (int i = 0; i < 4; i++)
            #pragma unroll
            for (int j = 0; j < 4; j++)
                s[i][j] += bias_s[63 + (tx*4 + j) - (ty*4 + i)];

        #pragma unroll
        for (int i = 0; i < 4; i++) {
            int r = ty*4 + i;
            float rmax = fmaxf(fmaxf(s[i][0], s[i][1]), fmaxf(s[i][2], s[i][3]));
            #pragma unroll
            for (int o = 8; o; o >>= 1)
                rmax = fmaxf(rmax, __shfl_xor_sync(0xffffffffu, rmax, o));
            float mold = m_s[r];
            float mnew = fmaxf(mold, rmax);
            float rsum = 0.f;
            #pragma unroll
            for (int j = 0; j < 4; j++) {
                s[i][j] = __expf(s[i][j] - mnew);
                rsum += s[i][j];
            }
            #pragma unroll
            for (int o = 8; o; o >>= 1)
                rsum += __shfl_xor_sync(0xffffffffu, rsum, o);
            if (tx == 0) {
                float scale = __expf(mold - mnew);
                sc_s[r] = scale;
                l_s[r]  = l_s[r] * scale + rsum;
                m_s[r]  = mnew;
            }
        }
        __syncthreads();

        #pragma unroll
        for (int i = 0; i < 4; i++)
            #pragma unroll
            for (int j = 0; j < 4; j++)
                Ps[(ty*4 + i)*TCOLS + tx*4 + j] = s[i][j];
        for (int i = tid; i < 64 * HD / 4; i += 256) {
            int r = i >> 4, c = (i & 15) * 4;
            float4 v = *(const float4*)(Vg + (size_t)(k0 + r) * HD + c);
            KVs[r*TCOLS + c + 0] = v.x;
            KVs[r*TCOLS + c + 1] = v.y;
            KVs[r*TCOLS + c + 2] = v.z;
            KVs[r*TCOLS + c + 3] = v.w;
        }
        __syncthreads();

        float scr[4];
        #pragma unroll
        for (int i = 0; i < 4; i++) scr[i] = sc_s[ty*4 + i];
        #pragma unroll
        for (int i = 0; i < 4; i++)
            #pragma unroll
            for (int j = 0; j < 4; j++) acc[i][j] *= scr[i];

        for (int jj = 0; jj < 64; jj++) {
            float pf[4], vf[4];
            #pragma unroll
            for (int i = 0; i < 4; i++) pf[i] = Ps[(ty*4 + i)*TCOLS + jj];
            #pragma unroll
            for (int j = 0; j < 4; j++) vf[j] = KVs[jj*TCOLS + tx*4 + j];
            #pragma unroll
            for (int i = 0; i < 4; i++)
                #pragma unroll
                for (int j = 0; j < 4; j++)
                    acc[i][j] += pf[i] * vf[j];
        }
    }

    __syncthreads();
    #pragma unroll
    for (int i = 0; i < 4; i++) {
        int r = ty*4 + i;
        float inv = 1.0f / l_s[r];
        #pragma unroll
        for (int j = 0; j < 4; j++) {
            g_ctx[((size_t)b * SEQ + q0 + r) * DMODEL + h*HD + tx*4 + j] = acc[i][j] * inv;
        }
    }
}

// ---------------- launch ----------------
extern "C" void kernel_launch(void* const* d_in, const int* in_sizes, int n_in,
                              void* d_out, int out_size)
{
    const float* x    = (const float*)d_in[0];
    const float* Wq   = (const float*)d_in[1];
    const float* Wk   = (const float*)d_in[2];
    const float* Wv   = (const float*)d_in[3];
    const float* Wo   = (const float*)d_in[4];
    const float* relE = (const float*)d_in[5];
    float* out = (float*)d_out;

    float *pq, *pk, *pv, *pctx;
    __nv_bfloat16 *pxh, *pxl, *pwh, *pwl, *pch, *pcl;
    cudaGetSymbolAddress((void**)&pq,   g_q);
    cudaGetSymbolAddress((void**)&pk,   g_k);
    cudaGetSymbolAddress((void**)&pv,   g_v);
    cudaGetSymbolAddress((void**)&pctx, g_ctx);
    cudaGetSymbolAddress((void**)&pxh,  g_xh);
    cudaGetSymbolAddress((void**)&pxl,  g_xl);
    cudaGetSymbolAddress((void**)&pwh,  g_wh);
    cudaGetSymbolAddress((void**)&pwl,  g_wl);
    cudaGetSymbolAddress((void**)&pch,  g_ch);
    cudaGetSymbolAddress((void**)&pcl,  g_cl);

    bias_kernel<<<(NH*2047 + 255)/256, 256>>>(relE);

    const int W = DMODEL*DMODEL;            // 1M
    split_kernel<<<(MTOT*DMODEL/4 + 255)/256, 256>>>(x, pxh, pxl, MTOT*DMODEL/4);
    split_kernel<<<(W/4 + 255)/256, 256>>>(Wq, pwh + 0*W, pwl + 0*W, W/4);
    split_kernel<<<(W/4 + 255)/256, 256>>>(Wk, pwh + 1*W, pwl + 1*W, W/4);
    split_kernel<<<(W/4 + 255)/256, 256>>>(Wv, pwh + 2*W, pwl + 2*W, W/4);
    split_kernel<<<(W/4 + 255)/256, 256>>>(Wo, pwh + 3*W, pwl + 3*W, W/4);

    cudaFuncSetAttribute(gemm_bf16split, cudaFuncAttributeMaxDynamicSharedMemorySize, 2*STAGE_BYTES);
    dim3 gg(DMODEL/128, MTOT/128);
    gemm_bf16split<<<gg, 256, 2*STAGE_BYTES>>>(pxh, pxl, pwh + 0*W, pwl + 0*W, pq, 1);
    gemm_bf16split<<<gg, 256, 2*STAGE_BYTES>>>(pxh, pxl, pwh + 1*W, pwl + 1*W, pk, 1);
    gemm_bf16split<<<gg, 256, 2*STAGE_BYTES>>>(pxh, pxl, pwh + 2*W, pwl + 2*W, pv, 1);

    cudaFuncSetAttribute(attn_kernel, cudaFuncAttributeMaxDynamicSharedMemorySize, 51200);
    attn_kernel<<<dim3(SEQ/64, NH, BATCH), 256, 51200>>>();

    split_kernel<<<(MTOT*DMODEL/4 + 255)/256, 256>>>(pctx, pch, pcl, MTOT*DMODEL/4);
    gemm_bf16split<<<gg, 256, 2*STAGE_BYTES>>>(pch, pcl, pwh + 3*W, pwl + 3*W, out, 0);
}

// round 4
// speedup vs baseline: 2.6885x; 1.8220x over previous
#include <cuda_runtime.h>
#include <cuda_bf16.h>
#include <cstdint>
#include <math.h>

#define BATCH  4
#define SEQ    1024
#define DMODEL 1024
#define NH     16
#define HD     64
#define MTOT   (BATCH*SEQ)

// ---------------- scratch ----------------
__device__ float g_bias[NH*2048];
__device__ __nv_bfloat16 g_xh[MTOT*DMODEL], g_xl[MTOT*DMODEL];
__device__ __nv_bfloat16 g_wh[4*DMODEL*DMODEL], g_wl[4*DMODEL*DMODEL];
__device__ __nv_bfloat16 g_qh[MTOT*DMODEL], g_ql[MTOT*DMODEL];   // [B,H,S,64]
__device__ __nv_bfloat16 g_kh[MTOT*DMODEL], g_kl[MTOT*DMODEL];   // [B,H,64,S] (transposed)
__device__ __nv_bfloat16 g_vh[MTOT*DMODEL], g_vl[MTOT*DMODEL];   // [B,H,S,64]
__device__ __nv_bfloat16 g_ch[MTOT*DMODEL], g_cl[MTOT*DMODEL];   // [B,S,H*64]

// ---------------- bias table ----------------
__global__ void bias_kernel(const float* __restrict__ rel_emb)
{
    int t = blockIdx.x * blockDim.x + threadIdx.x;
    if (t >= NH * 2047) return;
    int h   = t / 2047;
    int rel = (t % 2047) - 1023;
    int n   = -rel;
    int ret = 0;
    if (n < 0) { ret = 16; n = -n; }
    int bkt;
    if (n < 8) {
        bkt = n;
    } else {
        float v = logf((float)n * 0.125f) / logf(16.0f) * 8.0f;
        int vi = (int)v;
        bkt = 8 + (vi < 7 ? vi : 7);
    }
    g_bias[h*2048 + rel + 1023] = rel_emb[(ret + bkt)*NH + h];
}

// ---------------- fp32 -> bf16 hi/lo split ----------------
__global__ void split_kernel(const float* __restrict__ src,
                             __nv_bfloat16* __restrict__ hi,
                             __nv_bfloat16* __restrict__ lo, int n4)
{
    int i = blockIdx.x * blockDim.x + threadIdx.x;
    if (i >= n4) return;
    float4 v = ((const float4*)src)[i];
    __nv_bfloat16 h[4], l[4];
    float vv[4] = {v.x, v.y, v.z, v.w};
    #pragma unroll
    for (int j = 0; j < 4; j++) {
        h[j] = __float2bfloat16(vv[j]);
        l[j] = __float2bfloat16(vv[j] - __bfloat162float(h[j]));
    }
    ((uint2*)hi)[i] = *(uint2*)h;
    ((uint2*)lo)[i] = *(uint2*)l;
}

// ---------------- MMA helpers ----------------
#define LDSM4(r, addr) asm volatile( \
    "ldmatrix.sync.aligned.m8n8.x4.shared.b16 {%0,%1,%2,%3}, [%4];" \
    : "=r"(r[0]),"=r"(r[1]),"=r"(r[2]),"=r"(r[3]) : "r"(addr))
#define LDSM2T(r, addr) asm volatile( \
    "ldmatrix.sync.aligned.m8n8.x2.trans.shared.b16 {%0,%1}, [%2];" \
    : "=r"(r[0]),"=r"(r[1]) : "r"(addr))
#define MMA16816(d, a, b) asm volatile( \
    "mma.sync.aligned.m16n8k16.row.col.f32.bf16.bf16.f32 " \
    "{%0,%1,%2,%3},{%4,%5,%6,%7},{%8,%9},{%0,%1,%2,%3};" \
    : "+f"(d[0]),"+f"(d[1]),"+f"(d[2]),"+f"(d[3]) \
    : "r"(a[0]),"r"(a[1]),"r"(a[2]),"r"(a[3]),"r"(b[0]),"r"(b[1]))
#define CPASYNC16(dst, src) asm volatile( \
    "cp.async.cg.shared.global [%0], [%1], 16;" :: "r"(dst), "l"(src) : "memory")

__device__ __forceinline__ unsigned pack_hi(float x, float y) {
    __nv_bfloat162 t = __floats2bfloat162_rn(x, y);
    return *(unsigned*)&t;
}
__device__ __forceinline__ void split_pack(float x, float y, unsigned& h, unsigned& l) {
    __nv_bfloat16 hx = __float2bfloat16(x), hy = __float2bfloat16(y);
    __nv_bfloat16 lx = __float2bfloat16(x - __bfloat162float(hx));
    __nv_bfloat16 ly = __float2bfloat16(y - __bfloat162float(hy));
    __nv_bfloat162 th; th.x = hx; th.y = hy;
    __nv_bfloat162 tl; tl.x = lx; tl.y = ly;
    h = *(unsigned*)&th; l = *(unsigned*)&tl;
}

// ---------------- tensor-core split-bf16 GEMM ----------------
// smem per stage 37888: Ah 128*80 @0, Al @10240, Bh 32*272 @20480, Bl @29184
#define STAGE_BYTES 37888
__device__ __forceinline__ unsigned aOff(int buf, int arr, int row, int col) {
    return (unsigned)(buf*STAGE_BYTES + arr*10240 + row*80 + col*2);
}
__device__ __forceinline__ unsigned bOff(int buf, int arr, int row, int col) {
    return (unsigned)(buf*STAGE_BYTES + 20480 + arr*8704 + row*272 + col*2);
}

// mode 0: fp32 row-major to C
// mode 1: bf16 split, head layout [B,H,S,64] to Ch/Cl
// mode 2: bf16 split, K-transposed [B,H,64,S] to Ch/Cl
__global__ __launch_bounds__(256)
void gemm_bf16split(const __nv_bfloat16* __restrict__ Ah,
                    const __nv_bfloat16* __restrict__ Al,
                    const __nv_bfloat16* __restrict__ Bh,
                    const __nv_bfloat16* __restrict__ Bl,
                    float* __restrict__ C,
                    __nv_bfloat16* __restrict__ Ch,
                    __nv_bfloat16* __restrict__ Cl, int mode)
{
    extern __shared__ __align__(16) char smem_raw[];
    unsigned sbase = (unsigned)__cvta_generic_to_shared(smem_raw);

    const int tid  = threadIdx.x;
    const int wid  = tid >> 5, lane = tid & 31;
    const int wm0  = (wid & 3) * 32;
    const int wn0  = (wid >> 2) * 64;
    const int m0   = blockIdx.y * 128;
    const int n0   = blockIdx.x * 128;

    float acc[2][8][4];
    #pragma unroll
    for (int mi = 0; mi < 2; mi++)
        #pragma unroll
        for (int ni = 0; ni < 8; ni++)
            #pragma unroll
            for (int r = 0; r < 4; r++) acc[mi][ni][r] = 0.f;

    {
        #pragma unroll
        for (int u = 0; u < 2; u++) {
            int t = tid + u*256;
            int r = t >> 2, c = (t & 3) * 8;
            CPASYNC16(sbase + aOff(0,0,r,c), Ah + (size_t)(m0+r)*DMODEL + c);
            CPASYNC16(sbase + aOff(0,1,r,c), Al + (size_t)(m0+r)*DMODEL + c);
            int r2 = t >> 4, c2 = (t & 15) * 8;
            CPASYNC16(sbase + bOff(0,0,r2,c2), Bh + (size_t)r2*DMODEL + n0 + c2);
            CPASYNC16(sbase + bOff(0,1,r2,c2), Bl + (size_t)r2*DMODEL + n0 + c2);
        }
        asm volatile("cp.async.commit_group;" ::: "memory");
    }

    int buf = 0;
    for (int it = 0; it < DMODEL/32; it++) {
        if (it < DMODEL/32 - 1) {
            const int k0 = (it + 1) * 32;
            const int nb = buf ^ 1;
            #pragma unroll
            for (int u = 0; u < 2; u++) {
                int t = tid + u*256;
                int r = t >> 2, c = (t & 3) * 8;
                CPASYNC16(sbase + aOff(nb,0,r,c), Ah + (size_t)(m0+r)*DMODEL + k0 + c);
                CPASYNC16(sbase + aOff(nb,1,r,c), Al + (size_t)(m0+r)*DMODEL + k0 + c);
                int r2 = t >> 4, c2 = (t & 15) * 8;
                CPASYNC16(sbase + bOff(nb,0,r2,c2), Bh + (size_t)(k0+r2)*DMODEL + n0 + c2);
                CPASYNC16(sbase + bOff(nb,1,r2,c2), Bl + (size_t)(k0+r2)*DMODEL + n0 + c2);
            }
            asm volatile("cp.async.commit_group;" ::: "memory");
            asm volatile("cp.async.wait_group 1;" ::: "memory");
        } else {
            asm volatile("cp.async.wait_group 0;" ::: "memory");
        }
        __syncthreads();

        #pragma unroll
        for (int ks = 0; ks < 2; ks++) {
            unsigned afh[2][4], afl[2][4];
            #pragma unroll
            for (int mi = 0; mi < 2; mi++) {
                int row = wm0 + mi*16 + (lane & 15);
                int col = ks*16 + (lane >> 4) * 8;
                LDSM4(afh[mi], sbase + aOff(buf,0,row,col));
                LDSM4(afl[mi], sbase + aOff(buf,1,row,col));
            }
            unsigned bfh[8][2], bfl[8][2];
            #pragma unroll
            for (int ni = 0; ni < 8; ni++) {
                int row = ks*16 + (lane & 15);
                int col = wn0 + ni*8;
                LDSM2T(bfh[ni], sbase + bOff(buf,0,row,col));
                LDSM2T(bfl[ni], sbase + bOff(buf,1,row,col));
            }
            #pragma unroll
            for (int mi = 0; mi < 2; mi++)
                #pragma unroll
                for (int ni = 0; ni < 8; ni++) {
                    MMA16816(acc[mi][ni], afh[mi], bfh[ni]);
                    MMA16816(acc[mi][ni], afh[mi], bfl[ni]);
                    MMA16816(acc[mi][ni], afl[mi], bfh[ni]);
                }
        }
        __syncthreads();
        buf ^= 1;
    }

    // epilogue
    const int r  = lane >> 2;
    const int c2 = (lane & 3) * 2;
    #pragma unroll
    for (int mi = 0; mi < 2; mi++) {
        #pragma unroll
        for (int ni = 0; ni < 8; ni++) {
            int n = n0 + wn0 + ni*8 + c2;
            #pragma unroll
            for (int half = 0; half < 2; half++) {
                int m = m0 + wm0 + mi*16 + r + half*8;
                float v0 = acc[mi][ni][half*2], v1 = acc[mi][ni][half*2+1];
                if (mode == 0) {
                    *(float2*)(C + (size_t)m * DMODEL + n) = make_float2(v0, v1);
                } else if (mode == 1) {
                    size_t idx = (size_t)((m >> 10) * NH + (n >> 6)) * (SEQ * HD)
                               + (size_t)(m & 1023) * HD + (n & 63);
                    unsigned uh, ul;
                    split_pack(v0, v1, uh, ul);
                    *(unsigned*)(Ch + idx) = uh;
                    *(unsigned*)(Cl + idx) = ul;
                } else {
                    #pragma unroll
                    for (int e = 0; e < 2; e++) {
                        int ne = n + e;
                        float v = e ? v1 : v0;
                        size_t idx = (size_t)((m >> 10) * NH + (ne >> 6)) * (SEQ * HD)
                                   + (size_t)(ne & 63) * SEQ + (m & 1023);
                        __nv_bfloat16 hb = __float2bfloat16(v);
                        Ch[idx] = hb;
                        Cl[idx] = __float2bfloat16(v - __bfloat162float(hb));
                    }
                }
            }
        }
    }
}

// ---------------- tensor-core flash attention (split-bf16) ----------------
// smem layout (bytes): Qh 0 (128*144), Ql 18432, KTh 36864 (64*144), KTl 46080,
// Vh 55296, Vl 64512, bias 73728 (191 floats) -> total 74496
#define AQH 0
#define AQL 18432
#define AKH 36864
#define AKL 46080
#define AVH 55296
#define AVL 64512
#define ABIAS 73728
#define ATT_SMEM 74496
#define ASTRIDE 144   // bytes per row (72 bf16)

__global__ __launch_bounds__(256)
void attn_mma()
{
    extern __shared__ __align__(16) char asmem[];
    unsigned sb = (unsigned)__cvta_generic_to_shared(asmem);
    float* bias_s = (float*)(asmem + ABIAS);

    const int tid = threadIdx.x;
    const int wid = tid >> 5, lane = tid & 31;
    const int q0 = blockIdx.x * 128;
    const int h  = blockIdx.y;
    const int b  = blockIdx.z;
    const int bh = b*NH + h;

    const __nv_bfloat16* Qhp = g_qh + (size_t)bh * SEQ * HD;
    const __nv_bfloat16* Qlp = g_ql + (size_t)bh * SEQ * HD;
    const __nv_bfloat16* Khp = g_kh + (size_t)bh * HD * SEQ;   // [64][1024]
    const __nv_bfloat16* Klp = g_kl + (size_t)bh * HD * SEQ;
    const __nv_bfloat16* Vhp = g_vh + (size_t)bh * SEQ * HD;
    const __nv_bfloat16* Vlp = g_vl + (size_t)bh * SEQ * HD;

    // ---- load Q tile 128x64 ----
    for (int i = tid; i < 128*8; i += 256) {
        int r = i >> 3, c = (i & 7) * 8;
        CPASYNC16(sb + AQH + r*ASTRIDE + c*2, Qhp + (size_t)(q0 + r)*HD + c);
        CPASYNC16(sb + AQL + r*ASTRIDE + c*2, Qlp + (size_t)(q0 + r)*HD + c);
    }
    asm volatile("cp.async.commit_group;" ::: "memory");
    asm volatile("cp.async.wait_group 0;" ::: "memory");
    __syncthreads();

    // ---- hoist Q fragments ----
    const int wrow = wid * 16;
    unsigned qah[4][4], qal[4][4];
    #pragma unroll
    for (int kt = 0; kt < 4; kt++) {
        int row = wrow + (lane & 15);
        int col = kt*16 + (lane >> 4) * 8;
        LDSM4(qah[kt], sb + AQH + row*ASTRIDE + col*2);
        LDSM4(qal[kt], sb + AQL + row*ASTRIDE + col*2);
    }

    float oacc[8][4];
    #pragma unroll
    for (int nt = 0; nt < 8; nt++)
        #pragma unroll
        for (int e = 0; e < 4; e++) oacc[nt][e] = 0.f;
    float m0 = -1e30f, m1 = -1e30f, l0 = 0.f, l1 = 0.f;

    const int r = lane >> 2;
    const int cp = (lane & 3) * 2;
    const int il0 = wrow + r;

    for (int kc = 0; kc < SEQ/64; kc++) {
        const int k0 = kc * 64;
        __syncthreads();
        // load KT (64 d-rows x 64 seq) and V (64 seq-rows x 64 d)
        for (int i = tid; i < 64*8; i += 256) {
            int rr = i >> 3, cc = (i & 7) * 8;
            CPASYNC16(sb + AKH + rr*ASTRIDE + cc*2, Khp + (size_t)rr*SEQ + k0 + cc);
            CPASYNC16(sb + AKL + rr*ASTRIDE + cc*2, Klp + (size_t)rr*SEQ + k0 + cc);
            CPASYNC16(sb + AVH + rr*ASTRIDE + cc*2, Vhp + (size_t)(k0 + rr)*HD + cc);
            CPASYNC16(sb + AVL + rr*ASTRIDE + cc*2, Vlp + (size_t)(k0 + rr)*HD + cc);
        }
        if (tid < 191)
            bias_s[tid] = g_bias[h*2048 + 1023 + (k0 - q0) + tid - 127];
        asm volatile("cp.async.commit_group;" ::: "memory");
        asm volatile("cp.async.wait_group 0;" ::: "memory");
        __syncthreads();

        // ---- scores = Q K^T (3-term split) ----
        float sc[8][4];
        #pragma unroll
        for (int nt = 0; nt < 8; nt++)
            #pragma unroll
            for (int e = 0; e < 4; e++) sc[nt][e] = 0.f;

        #pragma unroll
        for (int ks = 0; ks < 4; ks++) {
            unsigned kbh[8][2], kbl[8][2];
            #pragma unroll
            for (int nt = 0; nt < 8; nt++) {
                int row = ks*16 + (lane & 15);
                LDSM2T(kbh[nt], sb + AKH + row*ASTRIDE + nt*16);
                LDSM2T(kbl[nt], sb + AKL + row*ASTRIDE + nt*16);
            }
            #pragma unroll
            for (int nt = 0; nt < 8; nt++) {
                MMA16816(sc[nt], qah[ks], kbh[nt]);
                MMA16816(sc[nt], qah[ks], kbl[nt]);
                MMA16816(sc[nt], qal[ks], kbh[nt]);
            }
        }

        // ---- bias + online softmax ----
        #pragma unroll
        for (int nt = 0; nt < 8; nt++) {
            int jl = nt*8 + cp;
            sc[nt][0] += bias_s[127 + jl     - il0];
            sc[nt][1] += bias_s[127 + jl + 1 - il0];
            sc[nt][2] += bias_s[127 + jl     - il0 - 8];
            sc[nt][3] += bias_s[127 + jl + 1 - il0 - 8];
        }
        float rm0 = -1e30f, rm1 = -1e30f;
        #pragma unroll
        for (int nt = 0; nt < 8; nt++) {
            rm0 = fmaxf(rm0, fmaxf(sc[nt][0], sc[nt][1]));
            rm1 = fmaxf(rm1, fmaxf(sc[nt][2], sc[nt][3]));
        }
        rm0 = fmaxf(rm0, __shfl_xor_sync(0xffffffffu, rm0, 1));
        rm0 = fmaxf(rm0, __shfl_xor_sync(0xffffffffu, rm0, 2));
        rm1 = fmaxf(rm1, __shfl_xor_sync(0xffffffffu, rm1, 1));
        rm1 = fmaxf(rm1, __shfl_xor_sync(0xffffffffu, rm1, 2));
        float mn0 = fmaxf(m0, rm0), mn1 = fmaxf(m1, rm1);
        float al0 = __expf(m0 - mn0), al1 = __expf(m1 - mn1);
        float s0 = 0.f, s1 = 0.f;
        #pragma unroll
        for (int nt = 0; nt < 8; nt++) {
            sc[nt][0] = __expf(sc[nt][0] - mn0); s0 += sc[nt][0];
            sc[nt][1] = __expf(sc[nt][1] - mn0); s0 += sc[nt][1];
            sc[nt][2] = __expf(sc[nt][2] - mn1); s1 += sc[nt][2];
            sc[nt][3] = __expf(sc[nt][3] - mn1); s1 += sc[nt][3];
        }
        s0 += __shfl_xor_sync(0xffffffffu, s0, 1);
        s0 += __shfl_xor_sync(0xffffffffu, s0, 2);
        s1 += __shfl_xor_sync(0xffffffffu, s1, 1);
        s1 += __shfl_xor_sync(0xffffffffu, s1, 2);
        l0 = l0 * al0 + s0;  l1 = l1 * al1 + s1;
        m0 = mn0;  m1 = mn1;
        #pragma unroll
        for (int nt = 0; nt < 8; nt++) {
            oacc[nt][0] *= al0; oacc[nt][1] *= al0;
            oacc[nt][2] *= al1; oacc[nt][3] *= al1;
        }

        // ---- O += P V (3-term split, P from registers) ----
        #pragma unroll
        for (int kt = 0; kt < 4; kt++) {
            unsigned pah[4], pal[4];
            split_pack(sc[2*kt  ][0], sc[2*kt  ][1], pah[0], pal[0]);
            split_pack(sc[2*kt  ][2], sc[2*kt  ][3], pah[1], pal[1]);
            split_pack(sc[2*kt+1][0], sc[2*kt+1][1], pah[2], pal[2]);
            split_pack(sc[2*kt+1][2], sc[2*kt+1][3], pah[3], pal[3]);
            unsigned vbh[8][2], vbl[8][2];
            #pragma unroll
            for (int nt = 0; nt < 8; nt++) {
                int row = kt*16 + (lane & 15);
                LDSM2T(vbh[nt], sb + AVH + row*ASTRIDE + nt*16);
                LDSM2T(vbl[nt], sb + AVL + row*ASTRIDE + nt*16);
            }
            #pragma unroll
            for (int nt = 0; nt < 8; nt++) {
                MMA16816(oacc[nt], pah, vbh[nt]);
                MMA16816(oacc[nt], pah, vbl[nt]);
                MMA16816(oacc[nt], pal, vbh[nt]);
            }
        }
    }

    // ---- epilogue: normalize + split-store to ctx ----
    float inv0 = 1.0f / l0, inv1 = 1.0f / l1;
    int s0r = q0 + wrow + r;
    #pragma unroll
    for (int nt = 0; nt < 8; nt++) {
        int col = h*HD + nt*8 + cp;
        unsigned uh, ul;
        split_pack(oacc[nt][0]*inv0, oacc[nt][1]*inv0, uh, ul);
        size_t idx0 = ((size_t)b * SEQ + s0r) * DMODEL + col;
        *(unsigned*)(g_ch + idx0) = uh;
        *(unsigned*)(g_cl + idx0) = ul;
        split_pack(oacc[nt][2]*inv1, oacc[nt][3]*inv1, uh, ul);
        size_t idx1 = ((size_t)b * SEQ + s0r + 8) * DMODEL + col;
        *(unsigned*)(g_ch + idx1) = uh;
        *(unsigned*)(g_cl + idx1) = ul;
    }
}

// ---------------- launch ----------------
extern "C" void kernel_launch(void* const* d_in, const int* in_sizes, int n_in,
                              void* d_out, int out_size)
{
    const float* x    = (const float*)d_in[0];
    const float* Wq   = (const float*)d_in[1];
    const float* Wk   = (const float*)d_in[2];
    const float* Wv   = (const float*)d_in[3];
    const float* Wo   = (const float*)d_in[4];
    const float* relE = (const float*)d_in[5];
    float* out = (float*)d_out;

    __nv_bfloat16 *pxh, *pxl, *pwh, *pwl;
    __nv_bfloat16 *pqh, *pql, *pkh, *pkl, *pvh, *pvl, *pch, *pcl;
    cudaGetSymbolAddress((void**)&pxh, g_xh);
    cudaGetSymbolAddress((void**)&pxl, g_xl);
    cudaGetSymbolAddress((void**)&pwh, g_wh);
    cudaGetSymbolAddress((void**)&pwl, g_wl);
    cudaGetSymbolAddress((void**)&pqh, g_qh);
    cudaGetSymbolAddress((void**)&pql, g_ql);
    cudaGetSymbolAddress((void**)&pkh, g_kh);
    cudaGetSymbolAddress((void**)&pkl, g_kl);
    cudaGetSymbolAddress((void**)&pvh, g_vh);
    cudaGetSymbolAddress((void**)&pvl, g_vl);
    cudaGetSymbolAddress((void**)&pch, g_ch);
    cudaGetSymbolAddress((void**)&pcl, g_cl);

    bias_kernel<<<(NH*2047 + 255)/256, 256>>>(relE);

    const int W = DMODEL*DMODEL;
    split_kernel<<<(MTOT*DMODEL/4 + 255)/256, 256>>>(x, pxh, pxl, MTOT*DMODEL/4);
    split_kernel<<<(W/4 + 255)/256, 256>>>(Wq, pwh + 0*W, pwl + 0*W, W/4);
    split_kernel<<<(W/4 + 255)/256, 256>>>(Wk, pwh + 1*W, pwl + 1*W, W/4);
    split_kernel<<<(W/4 + 255)/256, 256>>>(Wv, pwh + 2*W, pwl + 2*W, W/4);
    split_kernel<<<(W/4 + 255)/256, 256>>>(Wo, pwh + 3*W, pwl + 3*W, W/4);

    cudaFuncSetAttribute(gemm_bf16split, cudaFuncAttributeMaxDynamicSharedMemorySize, 2*STAGE_BYTES);
    dim3 gg(DMODEL/128, MTOT/128);
    gemm_bf16split<<<gg, 256, 2*STAGE_BYTES>>>(pxh, pxl, pwh + 0*W, pwl + 0*W, nullptr, pqh, pql, 1);
    gemm_bf16split<<<gg, 256, 2*STAGE_BYTES>>>(pxh, pxl, pwh + 1*W, pwl + 1*W, nullptr, pkh, pkl, 2);
    gemm_bf16split<<<gg, 256, 2*STAGE_BYTES>>>(pxh, pxl, pwh + 2*W, pwl + 2*W, nullptr, pvh, pvl, 1);

    cudaFuncSetAttribute(attn_mma, cudaFuncAttributeMaxDynamicSharedMemorySize, ATT_SMEM);
    attn_mma<<<dim3(SEQ/128, NH, BATCH), 256, ATT_SMEM>>>();

    gemm_bf16split<<<gg, 256, 2*STAGE_BYTES>>>(pch, pcl, pwh + 3*W, pwl + 3*W, out, nullptr, nullptr, 0);
}